// round 16
// baseline (speedup 1.0000x reference)
#include <cuda_runtime.h>
#include <math_constants.h>

#define HH 1024
#define WW 1024
#define NB 16
#define NPIX (NB * HH * WW)
#define TH 32
#define FULLM 0xffffffffu

__device__ __align__(256) float g_mid[NPIX];

#define C1 (1.0f / 24.0f)
#define C3 (3.0f / 24.0f)
#define C7 (7.0f / 24.0f)
#define NEGINF (-CUDART_INF_F)

typedef unsigned long long u64;

#define PK2(d, lo, hi)  asm("mov.b64 %0, {%1, %2};" : "=l"(d) : "f"(lo), "f"(hi))
#define UPK2(lo, hi, s) asm("mov.b64 {%0, %1}, %2;" : "=f"(lo), "=f"(hi) : "l"(s))
#define ADD2(d, a, b)   asm("add.rn.f32x2 %0, %1, %2;" : "=l"(d) : "l"(a), "l"(b))
#define ACC2(d, b)      asm("add.rn.f32x2 %0, %0, %1;" : "+l"(d) : "l"(b))
#define MUL2(d, a, b)   asm("mul.rn.f32x2 %0, %1, %2;" : "=l"(d) : "l"(a), "l"(b))
#define FMA2(d, a, b, c) asm("fma.rn.f32x2 %0, %1, %2, %3;" : "=l"(d) : "l"(a), "l"(b), "l"(c))

// ---- packed filter + 7-deep ring accumulate; returns completed slot ----
template<int U>
__device__ __forceinline__ void filt(const float w[10], u64 a[7][2],
                                     u64 kC1, u64 kC3, u64 kM7, u64 kM1,
                                     float raw[4])
{
    u64 P[9];
    #pragma unroll
    for (int j = 0; j < 9; ++j) PK2(P[j], w[j], w[j + 1]);

    #pragma unroll
    for (int p = 0; p < 2; ++p) {
        const int o = 2 * p;
        u64 t1, Pt, Puu, Pvv, Px2;
        ADD2(t1, P[2 + o], P[3 + o]);
        ADD2(Pt, t1, P[4 + o]);
        ADD2(Puu, P[1 + o], P[5 + o]);
        ADD2(Pvv, P[0 + o], P[6 + o]);
        ADD2(Px2, P[2 + o], P[4 + o]);

        u64 hA, hB, hC, hD, m1, m2, m3, i1, i2, i3;
        MUL2(hA, kC1, Pt);
        MUL2(m1, kC1, Puu);
        FMA2(hB, kC3, Pt, m1);
        MUL2(m2, kC1, P[0 + o]);
        FMA2(i1, kM7, P[3 + o], m2);
        FMA2(hC, kC3, Puu, i1);
        MUL2(m3, kC1, Pvv);
        FMA2(i2, kM7, Px2, m3);
        FMA2(i3, kC3, Puu, i2);
        FMA2(hD, kM1, P[3 + o], i3);

        ACC2(a[(U + 0) % 7][p], hA);
        ACC2(a[(U + 1) % 7][p], hB);
        ACC2(a[(U + 2) % 7][p], hC);
        ACC2(a[(U + 3) % 7][p], hD);
        ACC2(a[(U + 4) % 7][p], hC);
        ACC2(a[(U + 5) % 7][p], hB);
        ACC2(a[(U + 6) % 7][p], hA);
    }
    UPK2(raw[0], raw[1], a[U % 7][0]);
    UPK2(raw[2], raw[3], a[U % 7][1]);
    a[U % 7][0] = 0ull;
    a[U % 7][1] = 0ull;
}

struct FSt {
    u64 a1[7][2], a2[7][2];          // two conv rings
    float4 L, M, R;                  // prefetched next input row
    float cp1[4], pm1[4];            // stage-1 vmax state
    float cp2[4], pm2[4];            // stage-2 vmax state
    float mp[4];                     // m-row pipeline register (one step old)
    int bpp1, bpp2;                  // FIN: byte-packed bit history
};

// one fused, SW-pipelined step: stage2 consumes the m-row produced LAST step
template<int U1, int U2, int V1F, int M1F, int F2F, int V2F, int WF, int WRF,
         bool FIN, bool GEN>
__device__ __forceinline__ void fstep(FSt& s, const float*& p0, float*& wp, int& rr,
                                      const bool cv[4], bool Lok, bool Mok, bool Rok,
                                      bool writeok, int dup,
                                      u64 kC1, u64 kC3, u64 kM7, u64 kM1)
{
    const float4 Z = make_float4(0.f, 0.f, 0.f, 0.f);
    float w1[10] = { s.L.y, s.L.z, s.L.w, s.M.x, s.M.y, s.M.z, s.M.w,
                     s.R.x, s.R.y, s.R.z };
    if (GEN) {
        bool rv = (unsigned)(rr + 1) < (unsigned)HH;
        s.L = (rv && Lok) ? *reinterpret_cast<const float4*>(p0 - 4) : Z;
        s.M = (rv && Mok) ? *reinterpret_cast<const float4*>(p0)     : Z;
        s.R = (rv && Rok) ? *reinterpret_cast<const float4*>(p0 + 4) : Z;
    } else {
        s.L = *reinterpret_cast<const float4*>(p0 - 4);
        s.M = *reinterpret_cast<const float4*>(p0);
        s.R = *reinterpret_cast<const float4*>(p0 + 4);
    }
    p0 += WW;

    // stage-2 window from LAST step's m-row — shuffles overlap filt1 math
    float w2[10];
    if (F2F) {
        w2[0] = __shfl_up_sync(FULLM, s.mp[1], 1);
        w2[1] = __shfl_up_sync(FULLM, s.mp[2], 1);
        w2[2] = __shfl_up_sync(FULLM, s.mp[3], 1);
        w2[3] = s.mp[0]; w2[4] = s.mp[1]; w2[5] = s.mp[2]; w2[6] = s.mp[3];
        w2[7] = __shfl_down_sync(FULLM, s.mp[0], 1);
        w2[8] = __shfl_down_sync(FULLM, s.mp[1], 1);
        w2[9] = __shfl_down_sync(FULLM, s.mp[2], 1);
    }

    float raw1[4];
    filt<U1>(w1, s.a1, kC1, kC3, kM7, kM1, raw1);

    if (V1F) {
        float vm[4];
        #pragma unroll
        for (int k = 0; k < 4; ++k) {
            float c = raw1[k];
            if (GEN) {
                bool ok = ((unsigned)(rr - 3) < (unsigned)HH) && cv[k];
                c = ok ? c : NEGINF;
            }
            vm[k]   = fmaxf(s.pm1[k], c);
            s.pm1[k] = fmaxf(c, s.cp1[k]);
            s.cp1[k] = c;
        }
        if (M1F) {
            float vmL = __shfl_up_sync(FULLM, vm[3], 1);
            float vmR = __shfl_down_sync(FULLM, vm[0], 1);
            float m[4];
            m[0] = fmaxf(vmL,   fmaxf(vm[0], vm[1]));
            m[1] = fmaxf(vm[0], fmaxf(vm[1], vm[2]));
            m[2] = fmaxf(vm[1], fmaxf(vm[2], vm[3]));
            m[3] = fmaxf(vm[2], fmaxf(vm[3], vmR));
            if (GEN) {
                // stage-2 conv zero-pads outside the image
                bool mrv = (unsigned)(rr - 4) < (unsigned)HH;
                #pragma unroll
                for (int k = 0; k < 4; ++k) m[k] = (mrv && cv[k]) ? m[k] : 0.f;
            }
            #pragma unroll
            for (int k = 0; k < 4; ++k) s.mp[k] = m[k];   // feed next step
        }
    }

    if (F2F) {
        float raw2[4];
        filt<U2>(w2, s.a2, kC1, kC3, kM7, kM1, raw2);

        if (V2F) {
            float vm2[4];
            #pragma unroll
            for (int k = 0; k < 4; ++k) {
                float c = raw2[k];
                if (GEN) {
                    bool ok = ((unsigned)(rr - 8) < (unsigned)HH) && cv[k];
                    c = ok ? c : NEGINF;
                }
                vm2[k]   = fmaxf(s.pm2[k], c);
                s.pm2[k] = fmaxf(c, s.cp2[k]);
                s.cp2[k] = c;
            }
            if (WF) {
                float v2L = __shfl_up_sync(FULLM, vm2[3], 1);
                float v2R = __shfl_down_sync(FULLM, vm2[0], 1);
                float q0 = fmaxf(v2L,    fmaxf(vm2[0], vm2[1]));
                float q1 = fmaxf(vm2[0], fmaxf(vm2[1], vm2[2]));
                float q2 = fmaxf(vm2[1], fmaxf(vm2[2], vm2[3]));
                float q3 = fmaxf(vm2[2], fmaxf(vm2[3], v2R));

                if (!FIN) {
                    if (writeok)
                        *reinterpret_cast<float4*>(wp) = make_float4(q0, q1, q2, q3);
                } else {
                    bool bv = !GEN || ((unsigned)(rr - 9) < (unsigned)HH);
                    int b0 = (bv && (!GEN || cv[0]) && q0 > 0.5f) ? 1 : 0;
                    int b1 = (bv && (!GEN || cv[1]) && q1 > 0.5f) ? 1 : 0;
                    int b2 = (bv && (!GEN || cv[2]) && q2 > 0.5f) ? 1 : 0;
                    int b3 = (bv && (!GEN || cv[3]) && q3 > 0.5f) ? 1 : 0;
                    int bp = b0 | (b1 << 8) | (b2 << 16) | (b3 << 24);
                    int sp_ = s.bpp2 + s.bpp1 + bp;   // per-byte counts <=3
                    s.bpp2 = s.bpp1; s.bpp1 = bp;
                    int sLp = __shfl_up_sync(FULLM, sp_, 1);
                    int sRp = __shfl_down_sync(FULLM, sp_, 1);
                    if (WRF && writeok) {
                        unsigned u = (unsigned)sp_;
                        int s0 = u & 0xFF, s1 = (u >> 8) & 0xFF,
                            s2 = (u >> 16) & 0xFF, s3 = u >> 24;
                        int n0 = (int)(((unsigned)sLp) >> 24) + s0 + s1;
                        int n1 = s0 + s1 + s2;
                        int n2 = s1 + s2 + s3;
                        int n3 = s2 + s3 + (sRp & 0xFF);
                        float4 o = make_float4(n0 >= 8 ? 1.f : 0.f,
                                               n1 >= 8 ? 1.f : 0.f,
                                               n2 >= 8 ? 1.f : 0.f,
                                               n3 >= 8 ? 1.f : 0.f);
                        *reinterpret_cast<float4*>(wp) = o;
                        if (dup) *reinterpret_cast<float4*>(wp + NPIX) = o;
                    }
                }
                wp += WW;
            }
        }
    }
    if (GEN) ++rr;
}

template<bool FIN, bool GEN>
__device__ __forceinline__ void frun(const float* sp, float* dp, int c0, int Y0,
                                     int lane, int dup)
{
    const float4 Z = make_float4(0.f, 0.f, 0.f, 0.f);
    const bool writeok = (lane >= 2) && (lane <= 29) &&
                         (!GEN || (unsigned)c0 <= 1020u);
    bool cv[4];
    #pragma unroll
    for (int k = 0; k < 4; ++k) cv[k] = (unsigned)(c0 + k) < (unsigned)WW;
    const bool Lok = (unsigned)(c0 - 4) < (unsigned)WW;
    const bool Mok = (unsigned)c0 < (unsigned)WW;
    const bool Rok = (unsigned)(c0 + 4) < (unsigned)WW;

    u64 kC1, kC3, kM7, kM1;
    PK2(kC1, C1, C1); PK2(kC3, C3, C3); PK2(kM7, -C7, -C7); PK2(kM1, -1.0f, -1.0f);

    FSt s;
    #pragma unroll
    for (int i = 0; i < 7; ++i) {
        s.a1[i][0] = 0ull; s.a1[i][1] = 0ull;
        s.a2[i][0] = 0ull; s.a2[i][1] = 0ull;
    }
    #pragma unroll
    for (int k = 0; k < 4; ++k) {
        s.cp1[k] = NEGINF; s.pm1[k] = NEGINF;
        s.cp2[k] = NEGINF; s.pm2[k] = NEGINF;
        s.mp[k] = 0.f;
    }
    s.bpp1 = 0; s.bpp2 = 0;

    const int r0 = Y0 - (FIN ? 9 : 8);
    const float* pr = sp + (ptrdiff_t)r0 * WW + c0;
    if (GEN) {
        bool rv = (unsigned)r0 < (unsigned)HH;
        s.L = (rv && Lok) ? *reinterpret_cast<const float4*>(pr - 4) : Z;
        s.M = (rv && Mok) ? *reinterpret_cast<const float4*>(pr)     : Z;
        s.R = (rv && Rok) ? *reinterpret_cast<const float4*>(pr + 4) : Z;
    } else {
        s.L = *reinterpret_cast<const float4*>(pr - 4);
        s.M = *reinterpret_cast<const float4*>(pr);
        s.R = *reinterpret_cast<const float4*>(pr + 4);
    }
    const float* p0 = pr + WW;
    int rr = r0;
    float* wp = dp + (ptrdiff_t)(Y0 - (FIN ? 2 : 0)) * WW + c0;

    //                      U1  U2  V1 M1 F2 V2 WF WR
    #define SF(U1)        fstep<U1, 0,  0, 0, 0, 0, 0, 0, FIN, GEN>(s, p0, wp, rr, cv, Lok, Mok, Rok, writeok, dup, kC1, kC3, kM7, kM1);
    #define SV1(U1)       fstep<U1, 0,  1, 0, 0, 0, 0, 0, FIN, GEN>(s, p0, wp, rr, cv, Lok, Mok, Rok, writeok, dup, kC1, kC3, kM7, kM1);
    #define SM0(U1)       fstep<U1, 0,  1, 1, 0, 0, 0, 0, FIN, GEN>(s, p0, wp, rr, cv, Lok, Mok, Rok, writeok, dup, kC1, kC3, kM7, kM1);
    #define SM(U1, U2)    fstep<U1, U2, 1, 1, 1, 0, 0, 0, FIN, GEN>(s, p0, wp, rr, cv, Lok, Mok, Rok, writeok, dup, kC1, kC3, kM7, kM1);
    #define SV2(U1, U2)   fstep<U1, U2, 1, 1, 1, 1, 0, 0, FIN, GEN>(s, p0, wp, rr, cv, Lok, Mok, Rok, writeok, dup, kC1, kC3, kM7, kM1);
    #define SB(U1, U2)    fstep<U1, U2, 1, 1, 1, 1, 1, 0, FIN, GEN>(s, p0, wp, rr, cv, Lok, Mok, Rok, writeok, dup, kC1, kC3, kM7, kM1);
    #define SW(U1, U2)    fstep<U1, U2, 1, 1, 1, 1, 1, 1, FIN, GEN>(s, p0, wp, rr, cv, Lok, Mok, Rok, writeok, dup, kC1, kC3, kM7, kM1);

    // warm-up: 6 F, 2 V1, 1 M-only (primes mp), 6 M+filt2, 2 V2
    SF(0) SF(1) SF(2) SF(3) SF(4) SF(5)
    SV1(6) SV1(0)
    SM0(1)
    SM(2,0) SM(3,1) SM(4,2) SM(5,3) SM(6,4) SM(0,5)
    SV2(1,6) SV2(2,0)

    if (!FIN) {
        // steady: 32 writes
        #pragma unroll 1
        for (int g = 0; g < 4; ++g) {
            SW(3,1) SW(4,2) SW(5,3) SW(6,4) SW(0,5) SW(1,6) SW(2,0)
        }
        SW(3,1) SW(4,2) SW(5,3) SW(6,4)
    } else {
        // 2 bit-state steps, then 32 writes
        SB(3,1) SB(4,2)
        #pragma unroll 1
        for (int g = 0; g < 4; ++g) {
            SW(5,3) SW(6,4) SW(0,5) SW(1,6) SW(2,0) SW(3,1) SW(4,2)
        }
        SW(5,3) SW(6,4) SW(0,5) SW(1,6)
    }
    #undef SF
    #undef SV1
    #undef SM0
    #undef SM
    #undef SV2
    #undef SB
    #undef SW
}

template<bool FIN>
__global__ void __launch_bounds__(32, 14) fsweep(const float* __restrict__ src,
                                                 float* __restrict__ dst,
                                                 int dup)
{
    const int lane = threadIdx.x;
    const int sx = blockIdx.x;              // 0..9 strips of 112 output cols
    const int by = blockIdx.y;              // 0..31 chunks of 32 rows
    const int b  = blockIdx.z;
    const int Y0 = by * TH;
    const int c0 = 112 * sx - 8 + 4 * lane; // lane's 4 cols; valid lanes 2..29
    const float* sp = src + (size_t)b * HH * WW;
    float* dp = dst + (size_t)b * HH * WW;

    if (sx >= 1 && sx <= 8 && by >= 1 && by <= 30)
        frun<FIN, false>(sp, dp, c0, Y0, lane, dup);
    else
        frun<FIN, true>(sp, dp, c0, Y0, lane, dup);
}

extern "C" void kernel_launch(void* const* d_in, const int* in_sizes, int n_in,
                              void* d_out, int out_size)
{
    const float* x = (const float*)d_in[0];
    float* out = (float*)d_out;

    float* mid;
    cudaGetSymbolAddress((void**)&mid, g_mid);

    dim3 grid(10, HH / TH, NB);   // 5120 blocks
    dim3 block(32);
    int dup = (out_size >= 2 * NPIX) ? 1 : 0;

    fsweep<false><<<grid, block>>>(x, mid, 0);     // stages 1+2 fused
    fsweep<true ><<<grid, block>>>(mid, out, dup); // stages 3+4 + finalize fused
}

// round 17
// speedup vs baseline: 1.0825x; 1.0825x over previous
#include <cuda_runtime.h>
#include <math_constants.h>

#define HH 1024
#define WW 1024
#define NB 16
#define NPIX (NB * HH * WW)
#define TH 32
#define NOUT 6
#define FULLM 0xffffffffu

__device__ __align__(256) float g_bufA[NPIX];
__device__ __align__(256) float g_bufB[NPIX];

#define C1 (1.0f / 24.0f)
#define C3 (3.0f / 24.0f)
#define C7 (7.0f / 24.0f)
#define NEGINF (-CUDART_INF_F)

typedef unsigned long long u64;

#define PK2(d, lo, hi)  asm("mov.b64 %0, {%1, %2};" : "=l"(d) : "f"(lo), "f"(hi))
#define UPK2(lo, hi, s) asm("mov.b64 {%0, %1}, %2;" : "=f"(lo), "=f"(hi) : "l"(s))
#define ADD2(d, a, b)   asm("add.rn.f32x2 %0, %1, %2;" : "=l"(d) : "l"(a), "l"(b))
#define ACC2(d, b)      asm("add.rn.f32x2 %0, %0, %1;" : "+l"(d) : "l"(b))
#define MUL2(d, a, b)   asm("mul.rn.f32x2 %0, %1, %2;" : "=l"(d) : "l"(a), "l"(b))
#define FMA2(d, a, b, c) asm("fma.rn.f32x2 %0, %1, %2, %3;" : "=l"(d) : "l"(a), "l"(b), "l"(c))

// ---- packed filter + ring accumulate; returns completed slot in raw[4] ----
template<int U>
__device__ __forceinline__ void filt(const float w[10], u64 a[7][2],
                                     u64 kC1, u64 kC3, u64 kM7, u64 kM1,
                                     float raw[4])
{
    u64 P[9];
    #pragma unroll
    for (int j = 0; j < 9; ++j) PK2(P[j], w[j], w[j + 1]);

    #pragma unroll
    for (int p = 0; p < 2; ++p) {
        const int o = 2 * p;
        u64 t1, Pt, Puu, Pvv, Px2;
        ADD2(t1, P[2 + o], P[3 + o]);
        ADD2(Pt, t1, P[4 + o]);
        ADD2(Puu, P[1 + o], P[5 + o]);
        ADD2(Pvv, P[0 + o], P[6 + o]);
        ADD2(Px2, P[2 + o], P[4 + o]);

        u64 hA, hB, hC, hD, m1, m2, m3, i1, i2, i3;
        MUL2(hA, kC1, Pt);
        MUL2(m1, kC1, Puu);
        FMA2(hB, kC3, Pt, m1);
        MUL2(m2, kC1, P[0 + o]);
        FMA2(i1, kM7, P[3 + o], m2);
        FMA2(hC, kC3, Puu, i1);
        MUL2(m3, kC1, Pvv);
        FMA2(i2, kM7, Px2, m3);
        FMA2(i3, kC3, Puu, i2);
        FMA2(hD, kM1, P[3 + o], i3);

        ACC2(a[(U + 0) % 7][p], hA);
        ACC2(a[(U + 1) % 7][p], hB);
        ACC2(a[(U + 2) % 7][p], hC);
        ACC2(a[(U + 3) % 7][p], hD);
        ACC2(a[(U + 4) % 7][p], hC);
        ACC2(a[(U + 5) % 7][p], hB);
        ACC2(a[(U + 6) % 7][p], hA);
    }
    UPK2(raw[0], raw[1], a[U % 7][0]);
    UPK2(raw[2], raw[3], a[U % 7][1]);
    a[U % 7][0] = 0ull;
    a[U % 7][1] = 0ull;
}

// ======= INTERIOR path: 3-LDG window, bank ping-pong + L2 prefetch =========
struct StI {
    u64 a[7][2];
    float cp[4], pm[4];
    int bpp1, bpp2;      // FIN: byte-packed bit history
};

template<int U, bool FIN, bool VM, bool WR>
__device__ __forceinline__ void step_int(StI& s,
                                         float4& L, float4& M, float4& R,
                                         const float*& p0, float*& wp,
                                         bool writeok, int dup,
                                         u64 kC1, u64 kC3, u64 kM7, u64 kM1)
{
    // consume this bank (loaded 2 steps ago), then refill it with row r+2
    float w[10] = { L.y, L.z, L.w, M.x, M.y, M.z, M.w, R.x, R.y, R.z };
    L = *reinterpret_cast<const float4*>(p0 - 4);
    M = *reinterpret_cast<const float4*>(p0);
    R = *reinterpret_cast<const float4*>(p0 + 4);
    // pull row r+10 into L2 ahead of demand (warps jointly cover all lines)
    asm volatile("prefetch.global.L2 [%0];" :: "l"(p0 + 8 * WW));
    p0 += WW;

    float raw[4];
    filt<U>(w, s.a, kC1, kC3, kM7, kM1, raw);

    if (VM) {
        float vm[4];
        #pragma unroll
        for (int k = 0; k < 4; ++k) {
            vm[k]  = fmaxf(s.pm[k], raw[k]);
            s.pm[k] = fmaxf(raw[k], s.cp[k]);
            s.cp[k] = raw[k];
        }
        float vmL = __shfl_up_sync(FULLM, vm[3], 1);
        float vmR = __shfl_down_sync(FULLM, vm[0], 1);
        float m0 = fmaxf(vmL,   fmaxf(vm[0], vm[1]));
        float m1 = fmaxf(vm[0], fmaxf(vm[1], vm[2]));
        float m2 = fmaxf(vm[1], fmaxf(vm[2], vm[3]));
        float m3 = fmaxf(vm[2], fmaxf(vm[3], vmR));

        if (!FIN) {
            if (WR && writeok)
                *reinterpret_cast<float4*>(wp) = make_float4(m0, m1, m2, m3);
        } else {
            int bp = (m0 > 0.5f ? 1 : 0) | ((m1 > 0.5f ? 1 : 0) << 8)
                   | ((m2 > 0.5f ? 1 : 0) << 16) | ((m3 > 0.5f ? 1 : 0) << 24);
            int sp_ = s.bpp2 + s.bpp1 + bp;     // per-byte counts <= 3, carry-free
            s.bpp2 = s.bpp1; s.bpp1 = bp;
            int sLp = __shfl_up_sync(FULLM, sp_, 1);
            int sRp = __shfl_down_sync(FULLM, sp_, 1);
            if (WR && writeok) {
                unsigned u = (unsigned)sp_;
                int s0 = u & 0xFF, s1 = (u >> 8) & 0xFF,
                    s2 = (u >> 16) & 0xFF, s3 = u >> 24;
                int n0 = (int)(((unsigned)sLp) >> 24) + s0 + s1;
                int n1 = s0 + s1 + s2;
                int n2 = s1 + s2 + s3;
                int n3 = s2 + s3 + (sRp & 0xFF);
                float4 o = make_float4(n0 >= 8 ? 1.f : 0.f, n1 >= 8 ? 1.f : 0.f,
                                       n2 >= 8 ? 1.f : 0.f, n3 >= 8 ? 1.f : 0.f);
                *reinterpret_cast<float4*>(wp) = o;
                if (dup) *reinterpret_cast<float4*>(wp + NPIX) = o;
            }
        }
        wp += WW;
    }
}

template<bool FIN>
__device__ __forceinline__ void run_int(const float* sp, float* dp, int c0, int Y0,
                                        int lane, int dup)
{
    const bool writeok = (lane >= 1) && (lane <= 30);

    u64 kC1, kC3, kM7, kM1;
    PK2(kC1, C1, C1); PK2(kC3, C3, C3); PK2(kM7, -C7, -C7); PK2(kM1, -1.0f, -1.0f);

    StI s;
    #pragma unroll
    for (int i = 0; i < 7; ++i) { s.a[i][0] = 0ull; s.a[i][1] = 0ull; }
    #pragma unroll
    for (int k = 0; k < 4; ++k) { s.cp[k] = NEGINF; s.pm[k] = NEGINF; }
    s.bpp1 = 0; s.bpp2 = 0;

    const int rs = FIN ? (Y0 - 5) : (Y0 - 4);
    const float* pr = sp + (size_t)rs * WW + c0;
    float4 LA = *reinterpret_cast<const float4*>(pr - 4);        // row rs  (bank A)
    float4 MA = *reinterpret_cast<const float4*>(pr);
    float4 RA = *reinterpret_cast<const float4*>(pr + 4);
    float4 LB = *reinterpret_cast<const float4*>(pr + WW - 4);   // row rs+1 (bank B)
    float4 MB = *reinterpret_cast<const float4*>(pr + WW);
    float4 RB = *reinterpret_cast<const float4*>(pr + WW + 4);

    const float* p0 = pr + 2 * WW;    // next load = row rs+2
    float* wp = dp + (size_t)(FIN ? (Y0 - 4) : (Y0 - 2)) * WW + c0;

    #define SIA(UU, VMf, WRf) \
        step_int<UU, FIN, VMf, WRf>(s, LA, MA, RA, p0, wp, writeok, dup, kC1, kC3, kM7, kM1);
    #define SIB(UU, VMf, WRf) \
        step_int<UU, FIN, VMf, WRf>(s, LB, MB, RB, p0, wp, writeok, dup, kC1, kC3, kM7, kM1);

    if (!FIN) {
        SIA(0,false,false) SIB(1,false,false) SIA(2,false,false) SIB(3,false,false)
        SIA(4,false,false) SIB(5,false,false) SIA(6,true,false)  SIB(0,true,false)
        #pragma unroll 1
        for (int g = 0; g < 2; ++g) {   // 14-step body (even)
            SIA(1,true,true) SIB(2,true,true) SIA(3,true,true) SIB(4,true,true)
            SIA(5,true,true) SIB(6,true,true) SIA(0,true,true)
            SIB(1,true,true) SIA(2,true,true) SIB(3,true,true) SIA(4,true,true)
            SIB(5,true,true) SIA(6,true,true) SIB(0,true,true)
        }
        SIA(1,true,true) SIB(2,true,true) SIA(3,true,true) SIB(4,true,true)
    } else {
        SIA(0,false,false) SIB(1,false,false) SIA(2,false,false) SIB(3,false,false)
        SIA(4,false,false) SIB(5,false,false) SIA(6,true,false)  SIB(0,true,false)
        SIA(1,true,false)  SIB(2,true,false)
        #pragma unroll 1
        for (int g = 0; g < 2; ++g) {   // 14-step body (even)
            SIA(3,true,true) SIB(4,true,true) SIA(5,true,true) SIB(6,true,true)
            SIA(0,true,true) SIB(1,true,true) SIA(2,true,true)
            SIB(3,true,true) SIA(4,true,true) SIB(5,true,true) SIA(6,true,true)
            SIB(0,true,true) SIA(1,true,true) SIB(2,true,true)
        }
        SIA(3,true,true) SIB(4,true,true) SIA(5,true,true) SIB(6,true,true)
    }
    #undef SIA
    #undef SIB
}

// ===================== GENERIC path (full runtime guards) =====================
struct StG {
    u64 a[7][2];
    float4 ownN, extN;
    float cp[4], pm[4];
    int bp1[4], bp2[4];
};

__device__ __forceinline__ float4 ld4(const float* __restrict__ p, int r, int cc) {
    if ((unsigned)r < (unsigned)HH && (unsigned)cc < (unsigned)WW)
        return *reinterpret_cast<const float4*>(p + (size_t)r * WW + cc);
    return make_float4(0.f, 0.f, 0.f, 0.f);
}

template<int U, bool FIN>
__device__ __forceinline__ void step_gen(StG& s, const float* sp, float* dp, int r,
                                         int lane, int c0, int ecc, int Y0, int CFIRST,
                                         bool writeok, bool isEdge, const bool cv[4],
                                         int dup, u64 kC1, u64 kC3, u64 kM7, u64 kM1)
{
    float4 own = s.ownN, ext = s.extN;
    s.ownN = ld4(sp, r + 1, c0);
    s.extN = isEdge ? ld4(sp, r + 1, ecc) : make_float4(0.f, 0.f, 0.f, 0.f);

    float w[10];
    w[3] = own.x; w[4] = own.y; w[5] = own.z; w[6] = own.w;
    w[0] = __shfl_up_sync(FULLM, own.y, 1);
    w[1] = __shfl_up_sync(FULLM, own.z, 1);
    w[2] = __shfl_up_sync(FULLM, own.w, 1);
    w[7] = __shfl_down_sync(FULLM, own.x, 1);
    w[8] = __shfl_down_sync(FULLM, own.y, 1);
    w[9] = __shfl_down_sync(FULLM, own.z, 1);
    if (lane == 0)  { w[0] = ext.y; w[1] = ext.z; w[2] = ext.w; }
    if (lane == 31) { w[7] = ext.x; w[8] = ext.y; w[9] = ext.z; }

    float raw[4];
    filt<U>(w, s.a, kC1, kC3, kM7, kM1, raw);

    const int cr = r - 3;
    if (cr >= CFIRST) {
        const bool rv = (unsigned)cr < (unsigned)HH;
        float cur[4], vm[4];
        #pragma unroll
        for (int k = 0; k < 4; ++k) {
            cur[k] = (rv && cv[k]) ? raw[k] : NEGINF;
            vm[k]  = fmaxf(s.pm[k], cur[k]);
            s.pm[k] = fmaxf(cur[k], s.cp[k]);
            s.cp[k] = cur[k];
        }
        float vmL = __shfl_up_sync(FULLM, vm[3], 1);
        float vmR = __shfl_down_sync(FULLM, vm[0], 1);
        float m0 = fmaxf(vmL,   fmaxf(vm[0], vm[1]));
        float m1 = fmaxf(vm[0], fmaxf(vm[1], vm[2]));
        float m2 = fmaxf(vm[1], fmaxf(vm[2], vm[3]));
        float m3 = fmaxf(vm[2], fmaxf(vm[3], vmR));
        const int v = cr - 1;

        if (!FIN) {
            if (writeok && v >= Y0 && v < Y0 + TH && v < HH)
                *reinterpret_cast<float4*>(dp + (size_t)v * WW + c0)
                    = make_float4(m0, m1, m2, m3);
        } else {
            const bool bv = (unsigned)v < (unsigned)HH;
            int b0 = (bv && cv[0] && m0 > 0.5f) ? 1 : 0;
            int b1 = (bv && cv[1] && m1 > 0.5f) ? 1 : 0;
            int b2 = (bv && cv[2] && m2 > 0.5f) ? 1 : 0;
            int b3 = (bv && cv[3] && m3 > 0.5f) ? 1 : 0;
            int s0 = s.bp2[0] + s.bp1[0] + b0;
            int s1 = s.bp2[1] + s.bp1[1] + b1;
            int s2 = s.bp2[2] + s.bp1[2] + b2;
            int s3 = s.bp2[3] + s.bp1[3] + b3;
            s.bp2[0] = s.bp1[0]; s.bp2[1] = s.bp1[1];
            s.bp2[2] = s.bp1[2]; s.bp2[3] = s.bp1[3];
            s.bp1[0] = b0; s.bp1[1] = b1; s.bp1[2] = b2; s.bp1[3] = b3;
            int sL = __shfl_up_sync(FULLM, s3, 1);
            int sR = __shfl_down_sync(FULLM, s0, 1);
            int n0 = sL + s0 + s1;
            int n1 = s0 + s1 + s2;
            int n2 = s1 + s2 + s3;
            int n3 = s2 + s3 + sR;
            const int wr = v - 1;
            if (writeok && wr >= Y0 && wr < Y0 + TH && (unsigned)wr < (unsigned)HH) {
                float4 o = make_float4(n0 >= 8 ? 1.f : 0.f, n1 >= 8 ? 1.f : 0.f,
                                       n2 >= 8 ? 1.f : 0.f, n3 >= 8 ? 1.f : 0.f);
                float* op = dp + (size_t)wr * WW + c0;
                *reinterpret_cast<float4*>(op) = o;
                if (dup) *reinterpret_cast<float4*>(op + NPIX) = o;
            }
        }
    }
}

template<bool FIN>
__device__ __noinline__ void run_gen(const float* sp, float* dp, int c0, int Y0,
                                     int lane, int dup)
{
    const int ecc = (lane == 0) ? (c0 - 4) : (c0 + 4);
    const bool isEdge = (lane == 0) || (lane == 31);
    const bool writeok = (lane >= 1) && (lane <= 30) && (c0 < WW);
    bool cv[4];
    #pragma unroll
    for (int k = 0; k < 4; ++k) cv[k] = (unsigned)(c0 + k) < (unsigned)WW;
    const int CFIRST = FIN ? (Y0 - 2) : (Y0 - 1);

    u64 kC1, kC3, kM7, kM1;
    PK2(kC1, C1, C1); PK2(kC3, C3, C3); PK2(kM7, -C7, -C7); PK2(kM1, -1.0f, -1.0f);

    StG s;
    #pragma unroll
    for (int i = 0; i < 7; ++i) { s.a[i][0] = 0ull; s.a[i][1] = 0ull; }
    #pragma unroll
    for (int k = 0; k < 4; ++k) {
        s.cp[k] = NEGINF; s.pm[k] = NEGINF; s.bp1[k] = 0; s.bp2[k] = 0;
    }
    const int rs = FIN ? (Y0 - 5) : (Y0 - 4);
    s.ownN = ld4(sp, rs, c0);
    s.extN = isEdge ? ld4(sp, rs, ecc) : make_float4(0.f, 0.f, 0.f, 0.f);

    int r = rs;
    #pragma unroll 1
    for (int it = 0; it < NOUT; ++it) {
        step_gen<0, FIN>(s, sp, dp, r + 0, lane, c0, ecc, Y0, CFIRST, writeok, isEdge, cv, dup, kC1, kC3, kM7, kM1);
        step_gen<1, FIN>(s, sp, dp, r + 1, lane, c0, ecc, Y0, CFIRST, writeok, isEdge, cv, dup, kC1, kC3, kM7, kM1);
        step_gen<2, FIN>(s, sp, dp, r + 2, lane, c0, ecc, Y0, CFIRST, writeok, isEdge, cv, dup, kC1, kC3, kM7, kM1);
        step_gen<3, FIN>(s, sp, dp, r + 3, lane, c0, ecc, Y0, CFIRST, writeok, isEdge, cv, dup, kC1, kC3, kM7, kM1);
        step_gen<4, FIN>(s, sp, dp, r + 4, lane, c0, ecc, Y0, CFIRST, writeok, isEdge, cv, dup, kC1, kC3, kM7, kM1);
        step_gen<5, FIN>(s, sp, dp, r + 5, lane, c0, ecc, Y0, CFIRST, writeok, isEdge, cv, dup, kC1, kC3, kM7, kM1);
        step_gen<6, FIN>(s, sp, dp, r + 6, lane, c0, ecc, Y0, CFIRST, writeok, isEdge, cv, dup, kC1, kC3, kM7, kM1);
        r += 7;
    }
}

// ===================== combined kernel =====================
template<bool FIN>
__global__ void __launch_bounds__(32, 20) sweep(const float* __restrict__ src,
                                                float* __restrict__ dst,
                                                int dup)
{
    const int lane = threadIdx.x;
    const int sx = blockIdx.x;
    const int by = blockIdx.y;
    const int b  = blockIdx.z;
    const int Y0 = by * TH;
    const int c0 = 120 * sx - 4 + 4 * lane;
    const float* sp = src + (size_t)b * HH * WW;
    float* dp = dst + (size_t)b * HH * WW;

    if (sx >= 1 && sx <= 7 && by >= 1 && by <= 30)
        run_int<FIN>(sp, dp, c0, Y0, lane, dup);
    else
        run_gen<FIN>(sp, dp, c0, Y0, lane, dup);
}

extern "C" void kernel_launch(void* const* d_in, const int* in_sizes, int n_in,
                              void* d_out, int out_size)
{
    const float* x = (const float*)d_in[0];
    float* out = (float*)d_out;

    float *A, *B;
    cudaGetSymbolAddress((void**)&A, g_bufA);
    cudaGetSymbolAddress((void**)&B, g_bufB);

    dim3 grid(9, HH / TH, NB);
    int dup = (out_size >= 2 * NPIX) ? 1 : 0;

    sweep<false><<<grid, 32>>>(x, A, 0);
    sweep<false><<<grid, 32>>>(A, B, 0);
    sweep<false><<<grid, 32>>>(B, A, 0);
    sweep<true ><<<grid, 32>>>(A, out, dup);
}